// round 7
// baseline (speedup 1.0000x reference)
#include <cuda_runtime.h>

// Single fused kernel: build table + blend-interp, one launch.
// f(x) = sum_e B_e(x)*MLP_e(x); cubic B-spline => <=4 active experts/segment.
//   CTAs 0..16  : build raw table g_f[513] (32 pts x 4 slots x 4 lanes = 512 thr)
//   CTAs 17..591: front-batch their 4 x float4 loads (hides build under LDG lat)
//   all         : gate on g_flag (builders arrive; spinners nanosleep-poll),
//                 build (f,df) smem table, lerp, store.
// Reset protocol: the LAST CTA to pass the gate (atomicAdd ticket == GRID-1)
// resets g_flag/g_passed with plain stores -> no janitor spin, deterministic
// clean state for every graph replay. Deadlock-free at ANY occupancy: builders
// are the lowest block ids (first wave), never wait before setting the flag.

#define TAB    512
#define NEXP   7
#define NSM    148
#define GRID   (4 * NSM)          // 592
#define BLK    512
#define BCTAS  17                 // 16 x 32 points + 1 endpoint CTA

__device__ float g_f[TAB + 1];
__device__ int   g_flag;          // builders done counter
__device__ int   g_passed;        // gate-passed ticket counter

// fast tanh: 1 - 2/(exp(2x)+1). EX2+RCP: abs err ~1e-7, overflow-safe.
__device__ __forceinline__ float fast_tanh(float x) {
    float e = __expf(2.0f * x);
    return 1.0f - __fdividef(2.0f, e + 1.0f);
}

// Cox-de Boor degree 3, matching reference half-open intervals + safe division.
__device__ __forceinline__ float bspline3(float x, const float* kn, int i) {
    float N[4];
#pragma unroll
    for (int j = 0; j < 4; j++)
        N[j] = (kn[i + j] <= x && x < kn[i + j + 1]) ? 1.0f : 0.0f;
#pragma unroll
    for (int d = 1; d <= 3; d++) {
#pragma unroll
        for (int j = 0; j <= 3 - d; j++) {
            float d1 = kn[i + j + d] - kn[i + j];
            float d2 = kn[i + j + d + 1] - kn[i + j + 1];
            float t1 = (d1 != 0.0f) ? (x - kn[i + j]) / d1 * N[j] : 0.0f;
            float t2 = (d2 != 0.0f) ? (kn[i + j + d + 1] - x) / d2 * N[j + 1] : 0.0f;
            N[j] = t1 + t2;
        }
    }
    return N[0];
}

__device__ __forceinline__ float lerp_tab(float x, const float2* tab) {
    float t = x * (float)TAB;
    int i = min((int)t, TAB - 1);      // x in [0,1); min = insurance
    float fr = t - (float)i;
    float2 p = tab[i];                 // single LDS.64
    return fmaf(fr, p.y, p.x);
}

__global__ void __launch_bounds__(BLK, 4)
fused_kernel(const float4* __restrict__ x4, float4* __restrict__ o4, int n4,
             const float* __restrict__ xs, float* __restrict__ os, int n,
             const float* __restrict__ knots,
             const float* __restrict__ W1, const float* __restrict__ b1,
             const float* __restrict__ W2, const float* __restrict__ b2,
             const float* __restrict__ W3, const float* __restrict__ b3) {
    __shared__ float2 tab[TAB];                       // 4 KB
    __shared__ float  sW1[NEXP * 16], sb1[NEXP * 16], sW2[NEXP * 256],
                      sb2[NEXP * 16], sW3[NEXP * 16], sb3[NEXP], skn[16];
    __shared__ float  spart[32][4];

    int t = threadIdx.x;
    int b = blockIdx.x;
    int tid = b * BLK + t;
    const int S = GRID * BLK;

    bool builder = (b < BCTAS);
    float4 v[4];
    bool   m[4];
#pragma unroll
    for (int k = 0; k < 4; k++) m[k] = (tid + k * S < n4);

    if (!builder) {
        // front-batched LDG.128 x4; latency overlaps the builders' work
#pragma unroll
        for (int k = 0; k < 4; k++)
            if (m[k]) v[k] = x4[tid + k * S];
    } else {
        // ---------------- build phase ----------------
        for (int i = t; i < NEXP * 16; i += BLK) {
            sW1[i] = W1[i]; sb1[i] = b1[i]; sb2[i] = b2[i]; sW3[i] = W3[i];
        }
        for (int i = t; i < NEXP * 256; i += BLK) sW2[i] = W2[i];
        if (t < NEXP) sb3[t] = b3[t];
        if (t < 11)   skn[t] = knots[t];
        __syncthreads();

        int quad = t >> 2, l4 = t & 3;
        int p    = quad >> 2;          // local point 0..31
        int slot = quad & 3;           // active-expert slot
        int gi   = b * 32 + p;         // global table index
        int qb   = t & 28;
        unsigned qmask = 0xFu << (qb & 31);

        float val = 0.0f;
        if (gi <= TAB) {
            float x = (float)gi * (1.0f / (float)TAB);
            int seg = min((gi * 10) >> 9, 9);
            int e   = seg - slot;
            if (e >= 0 && e <= 6) {
                float h1loc[4];
#pragma unroll
                for (int r = 0; r < 4; r++) {
                    int k = l4 * 4 + r;
                    h1loc[r] = fast_tanh(fmaf(sW1[e * 16 + k], x, sb1[e * 16 + k]));
                }
                float acc[4];
#pragma unroll
                for (int r = 0; r < 4; r++) acc[r] = sb2[e * 16 + l4 * 4 + r];
#pragma unroll
                for (int k = 0; k < 16; k++) {
                    float h1k = __shfl_sync(qmask, h1loc[k & 3], qb + (k >> 2));
#pragma unroll
                    for (int r = 0; r < 4; r++)
                        acc[r] = fmaf(sW2[e * 256 + (l4 * 4 + r) * 16 + k], h1k, acc[r]);
                }
                float yp = 0.0f;
#pragma unroll
                for (int r = 0; r < 4; r++)
                    yp = fmaf(sW3[e * 16 + l4 * 4 + r], fast_tanh(acc[r]), yp);
                yp += __shfl_xor_sync(qmask, yp, 1);
                yp += __shfl_xor_sync(qmask, yp, 2);
                val = (yp + sb3[e]) * bspline3(x, skn, e);
            }
        }
        if (l4 == 0) spart[p][slot] = val;
        __syncthreads();

        if (t < 32) {
            int gi2 = b * 32 + t;
            if (gi2 <= TAB) {
                g_f[gi2] = spart[t][0] + spart[t][1] + spart[t][2] + spart[t][3];
            }
            __threadfence();                           // release: table writes
        }
        __syncthreads();                               // writers' fence before arrive
        if (t == 0) atomicAdd(&g_flag, 1);
    }

    // ---------------- gate ----------------
    if (t == 0) {
        if (atomicAdd(&g_flag, 0) < BCTAS) {           // fast path check
            while (atomicAdd(&g_flag, 0) < BCTAS) __nanosleep(64);
        }
        __threadfence();                               // acquire
    }
    __syncthreads();

    // build (f, df) smem table from raw g_f (coalesced, L2-broadcast)
    {
        float f0 = g_f[t];
        float f1 = g_f[t + 1];
        tab[t] = make_float2(f0, f1 - f0);
    }
    __syncthreads();

    // ticket: last CTA through the gate resets state for the next replay
    if (t == 0) {
        int ticket = atomicAdd(&g_passed, 1);
        if (ticket == GRID - 1) {
            g_flag = 0;
            g_passed = 0;
            __threadfence();
        }
    }

    if (builder) {                                     // builders load x late
#pragma unroll
        for (int k = 0; k < 4; k++)
            if (m[k]) v[k] = x4[tid + k * S];
    }

    // ---------------- interp ----------------
#pragma unroll
    for (int k = 0; k < 4; k++) {
        if (m[k]) {
            float4 r;
            r.x = lerp_tab(v[k].x, tab);
            r.y = lerp_tab(v[k].y, tab);
            r.z = lerp_tab(v[k].z, tab);
            r.w = lerp_tab(v[k].w, tab);
            o4[tid + k * S] = r;
        }
    }
    if (b == BCTAS) {                                  // tail (n % 4 != 0)
        for (int j = n4 * 4 + t; j < n; j += BLK)
            os[j] = lerp_tab(xs[j], tab);
    }
}

extern "C" void kernel_launch(void* const* d_in, const int* in_sizes, int n_in,
                              void* d_out, int out_size) {
    // metadata order: x, knots, W1, b1, W2, b2, W3, b3
    const float* x     = (const float*)d_in[0];
    const float* knots = (const float*)d_in[1];
    const float* W1    = (const float*)d_in[2];
    const float* b1    = (const float*)d_in[3];
    const float* W2    = (const float*)d_in[4];
    const float* b2    = (const float*)d_in[5];
    const float* W3    = (const float*)d_in[6];
    const float* b3    = (const float*)d_in[7];
    float* out = (float*)d_out;
    int n = out_size;
    int n4 = n >> 2;

    fused_kernel<<<GRID, BLK>>>((const float4*)x, (float4*)out, n4,
                                x, out, n, knots, W1, b1, W2, b2, W3, b3);
}